// round 9
// baseline (speedup 1.0000x reference)
#include <cuda_runtime.h>

#define BATCH 32
#define IMH 1024
#define IMW 1024
#define NBOX 96
#define WARPS 8
#define NTHREADS 256
#define ROWS_PER_WARP 8
#define ROWS_PER_BLOCK (WARPS * ROWS_PER_WARP)   // 64
#define GRID (BATCH * IMH / ROWS_PER_BLOCK)      // 512
#define EP_STRIDE 1032                           // >=1025, float4-aligned
#define PF_DIST 5                                // L2 prefetch distance in rows

// Per-(batch,box) rectangle sums. Zero-initialized at module load; the last
// block resets it after reading so every graph replay starts clean.
__device__ float    g_boxsum[BATCH * NBOX];
__device__ unsigned g_done;

__device__ __forceinline__ void pf_l2(const float* p) {
    asm volatile("prefetch.global.L2 [%0];" :: "l"(p));
}

__global__ __launch_bounds__(NTHREADS)
void fused_kernel(const float* __restrict__ img, const int* __restrict__ bb,
                  float* __restrict__ out) {
    __shared__ __align__(16) float ep_s[WARPS * EP_STRIDE];
    __shared__ int4 sbox[NBOX];

    const int t    = threadIdx.x;
    const int lane = t & 31;
    const int w    = t >> 5;
    const int blocksPerBatch = IMH / ROWS_PER_BLOCK;   // 16
    const int b       = blockIdx.x / blocksPerBatch;
    const int rowBase = (blockIdx.x % blocksPerBatch) * ROWS_PER_BLOCK + w * ROWS_PER_WARP;

    float* ep = ep_s + w * EP_STRIDE;

    const float*  gimg   = img + (size_t)b * IMH * IMW;
    const float4* imgrow = (const float4*)gimg;
    const int     gRowMax = BATCH * IMH - 1;          // clamp for prefetch (stay in img)
    const int     gRow0   = b * IMH + rowBase;        // global row index of this warp

    // Issue first-row demand loads + deep L2 prefetches BEFORE the bbox sync.
    float4 va[8];
#pragma unroll
    for (int j = 0; j < 8; j++)
        va[j] = imgrow[(size_t)rowBase * (IMW / 4) + lane + 32 * j];
#pragma unroll
    for (int p = 1; p <= PF_DIST; p++) {
        int gr = min(gRow0 + p, gRowMax);
        pf_l2(img + (size_t)gr * IMW + lane * 32);    // one line (128B) per lane = whole row
    }

    if (t < NBOX) sbox[t] = ((const int4*)bb)[b * NBOX + t];
    __syncthreads();

    // Each lane serves boxes lane, lane+32, lane+64.
    int   bx1[3], bx2[3], by1[3], by2[3];
    bool  bval[3];
    float bacc[3];
#pragma unroll
    for (int k = 0; k < 3; k++) {
        int4 box = sbox[lane + 32 * k];
        bx1[k] = min(max(box.x, 0), IMW);
        by1[k] = min(max(box.y, 0), IMW);
        bx2[k] = min(max(box.z, 0), IMW);
        by2[k] = min(max(box.w, 0), IMW);
        bval[k] = (bx2[k] > bx1[k]) && (by2[k] > by1[k]);
        bacc[k] = 0.0f;
    }

#pragma unroll
    for (int r = 0; r < ROWS_PER_WARP; ++r) {
        const int row = rowBase + r;

        // L2 prefetch PF_DIST+1 rows ahead of the demand stream.
        {
            int gr = min(gRow0 + r + PF_DIST + 1, gRowMax);
            pf_l2(img + (size_t)gr * IMW + lane * 32);
        }

        // Register prefetch of next row (demand load, should be ~L2 hit now).
        float4 vb[8];
        if (r + 1 < ROWS_PER_WARP) {
#pragma unroll
            for (int j = 0; j < 8; j++)
                vb[j] = imgrow[(size_t)(row + 1) * (IMW / 4) + lane + 32 * j];
        }

        // Segment sums + eight warp scans chained through a scalar base.
        float excl[8];
        float base = 0.0f;
#pragma unroll
        for (int j = 0; j < 8; j++) {
            float sj = (va[j].x + va[j].y) + (va[j].z + va[j].w);
            float sc = sj;
#pragma unroll
            for (int o = 1; o < 32; o <<= 1) {
                float u = __shfl_up_sync(0xffffffffu, sc, o);
                if (lane >= o) sc += u;
            }
            excl[j] = (sc - sj) + base;
            base += __shfl_sync(0xffffffffu, sc, 31);   // segment total
        }

        // Write exclusive prefixes: 8 conflict-free STS.128 per row.
#pragma unroll
        for (int j = 0; j < 8; j++) {
            float4 p;
            p.x = excl[j];
            p.y = p.x + va[j].x;
            p.z = p.y + va[j].y;
            p.w = p.z + va[j].z;
            *(float4*)(ep + 128 * j + 4 * lane) = p;
        }
        if (lane == 31) ep[IMW] = base;
        __syncwarp();

        // Serve this row for all 96 boxes (3 per lane).
#pragma unroll
        for (int k = 0; k < 3; k++) {
            if (bval[k] && by1[k] <= row && row < by2[k])
                bacc[k] += ep[bx2[k]] - ep[bx1[k]];
        }
        __syncwarp();   // ep reused next row

        if (r + 1 < ROWS_PER_WARP) {
#pragma unroll
            for (int j = 0; j < 8; j++)
                va[j] = vb[j];
        }
    }

#pragma unroll
    for (int k = 0; k < 3; k++)
        if (bval[k] && bacc[k] != 0.0f)
            atomicAdd(&g_boxsum[b * NBOX + lane + 32 * k], bacc[k]);

    // ---- last-block epilogue: loss + state reset ----
    __shared__ unsigned lastflag;
    __threadfence();
    if (t == 0) {
        unsigned vdone = atomicAdd(&g_done, 1u);
        lastflag = (vdone == (unsigned)(gridDim.x - 1));
    }
    __syncthreads();

    if (lastflag) {
        float sum = 0.0f;
#pragma unroll 4
        for (int i = t; i < BATCH * NBOX; i += NTHREADS) {
            float sv = __ldcg(&g_boxsum[i]);
            g_boxsum[i] = 0.0f;                 // reset for next replay
            float d = 1.0f - sv;                // invalid boxes stayed 0 -> contribute 1
            sum += (d > 0.0f) ? d : 0.0f;
        }
        __shared__ float red[WARPS];
#pragma unroll
        for (int o = 16; o; o >>= 1) sum += __shfl_down_sync(0xffffffffu, sum, o);
        if (lane == 0) red[w] = sum;
        __syncthreads();
        if (w == 0) {
            sum = (lane < WARPS) ? red[lane] : 0.0f;
#pragma unroll
            for (int o = 16; o; o >>= 1) sum += __shfl_down_sync(0xffffffffu, sum, o);
            if (lane == 0) {
                *out = sum;
                g_done = 0u;                    // reset counter for next replay
            }
        }
    }
}

extern "C" void kernel_launch(void* const* d_in, const int* in_sizes, int n_in,
                              void* d_out, int out_size) {
    const float* img = (const float*)d_in[0];   // (32,1,1024,1024) fp32
    const int*   bb  = (const int*)d_in[1];     // (32,96,4) int32
    float* out = (float*)d_out;

    fused_kernel<<<GRID, NTHREADS>>>(img, bb, out);
}

// round 10
// speedup vs baseline: 1.1373x; 1.1373x over previous
#include <cuda_runtime.h>

#define BATCH 32
#define IMH 1024
#define IMW 1024
#define NBOX 96
#define WARPS 8
#define NTHREADS 256
#define ROWS_PER_WARP 4
#define ROWS_PER_BLOCK (WARPS * ROWS_PER_WARP)   // 32
#define GRID (BATCH * IMH / ROWS_PER_BLOCK)      // 1024
#define EP_STRIDE 1032                           // >=1025, float4-aligned

// Per-(batch,box) rectangle sums. Zero-initialized at module load; the last
// block resets it after reading so every graph replay starts clean.
__device__ float    g_boxsum[BATCH * NBOX];
__device__ unsigned g_done;

__global__ __launch_bounds__(NTHREADS)
void fused_kernel(const float* __restrict__ img, const int* __restrict__ bb,
                  float* __restrict__ out) {
    __shared__ __align__(16) float ep_s[WARPS * EP_STRIDE];
    __shared__ int4 sbox[NBOX];

    const int t    = threadIdx.x;
    const int lane = t & 31;
    const int w    = t >> 5;
    const int blocksPerBatch = IMH / ROWS_PER_BLOCK;   // 32
    const int b       = blockIdx.x / blocksPerBatch;
    const int rowBase = (blockIdx.x % blocksPerBatch) * ROWS_PER_BLOCK + w * ROWS_PER_WARP;

    float* ep = ep_s + w * EP_STRIDE;

    const float4* imgrow = (const float4*)(img + (size_t)b * IMH * IMW);

    // First-row loads issued before the bbox sync (prologue overlap).
    float4 va[8];
#pragma unroll
    for (int j = 0; j < 8; j++)
        va[j] = imgrow[(size_t)rowBase * (IMW / 4) + lane + 32 * j];

    if (t < NBOX) sbox[t] = ((const int4*)bb)[b * NBOX + t];
    __syncthreads();

    // Each lane serves boxes lane, lane+32, lane+64.
    int   bx1[3], bx2[3], by1[3], by2[3];
    bool  bval[3];
    float bacc[3];
#pragma unroll
    for (int k = 0; k < 3; k++) {
        int4 box = sbox[lane + 32 * k];
        bx1[k] = min(max(box.x, 0), IMW);
        by1[k] = min(max(box.y, 0), IMW);
        bx2[k] = min(max(box.z, 0), IMW);
        by2[k] = min(max(box.w, 0), IMW);
        bval[k] = (bx2[k] > bx1[k]) && (by2[k] > by1[k]);
        bacc[k] = 0.0f;
    }

#pragma unroll
    for (int r = 0; r < ROWS_PER_WARP; ++r) {
        const int row = rowBase + r;

        // Register prefetch of next row (overlaps this row's scan).
        float4 vb[8];
        if (r + 1 < ROWS_PER_WARP) {
#pragma unroll
            for (int j = 0; j < 8; j++)
                vb[j] = imgrow[(size_t)(row + 1) * (IMW / 4) + lane + 32 * j];
        }

        // Per-(lane, segment) 4-element sums.
        float s[8], sc[8];
#pragma unroll
        for (int j = 0; j < 8; j++) {
            s[j]  = (va[j].x + va[j].y) + (va[j].z + va[j].w);
            sc[j] = s[j];
        }

        // EIGHT CONCURRENT Kogge-Stone scans: o-outer, j-inner so the 8
        // independent shfl chains pipeline in the SMSP (latency ~5*26 total,
        // not 8 serialized scans).
#pragma unroll
        for (int o = 1; o < 32; o <<= 1) {
#pragma unroll
            for (int j = 0; j < 8; j++) {
                float u = __shfl_up_sync(0xffffffffu, sc[j], o);
                if (lane >= o) sc[j] += u;
            }
        }

        // Segment totals via 8 parallel broadcasts, then a short scalar
        // exclusive prefix over the 8 totals (7 FADDs).
        float T[8];
#pragma unroll
        for (int j = 0; j < 8; j++)
            T[j] = __shfl_sync(0xffffffffu, sc[j], 31);
        float basej[8];
        basej[0] = 0.0f;
#pragma unroll
        for (int j = 1; j < 8; j++)
            basej[j] = basej[j - 1] + T[j - 1];
        const float rowtot = basej[7] + T[7];

        // Write exclusive prefixes: 8 conflict-free STS.128 per row.
#pragma unroll
        for (int j = 0; j < 8; j++) {
            float excl = (sc[j] - s[j]) + basej[j];
            float4 p;
            p.x = excl;
            p.y = p.x + va[j].x;
            p.z = p.y + va[j].y;
            p.w = p.z + va[j].z;
            *(float4*)(ep + 128 * j + 4 * lane) = p;
        }
        if (lane == 31) ep[IMW] = rowtot;
        __syncwarp();

        // Serve this row for all 96 boxes (3 per lane).
#pragma unroll
        for (int k = 0; k < 3; k++) {
            if (bval[k] && by1[k] <= row && row < by2[k])
                bacc[k] += ep[bx2[k]] - ep[bx1[k]];
        }
        __syncwarp();   // ep reused next row

        if (r + 1 < ROWS_PER_WARP) {
#pragma unroll
            for (int j = 0; j < 8; j++)
                va[j] = vb[j];
        }
    }

#pragma unroll
    for (int k = 0; k < 3; k++)
        if (bval[k] && bacc[k] != 0.0f)
            atomicAdd(&g_boxsum[b * NBOX + lane + 32 * k], bacc[k]);

    // ---- last-block epilogue: loss + state reset ----
    __shared__ unsigned lastflag;
    __threadfence();
    if (t == 0) {
        unsigned vdone = atomicAdd(&g_done, 1u);
        lastflag = (vdone == (unsigned)(gridDim.x - 1));
    }
    __syncthreads();

    if (lastflag) {
        float sum = 0.0f;
#pragma unroll 4
        for (int i = t; i < BATCH * NBOX; i += NTHREADS) {
            float sv = __ldcg(&g_boxsum[i]);
            g_boxsum[i] = 0.0f;                 // reset for next replay
            float d = 1.0f - sv;                // invalid boxes stayed 0 -> contribute 1
            sum += (d > 0.0f) ? d : 0.0f;
        }
        __shared__ float red[WARPS];
#pragma unroll
        for (int o = 16; o; o >>= 1) sum += __shfl_down_sync(0xffffffffu, sum, o);
        if (lane == 0) red[w] = sum;
        __syncthreads();
        if (w == 0) {
            sum = (lane < WARPS) ? red[lane] : 0.0f;
#pragma unroll
            for (int o = 16; o; o >>= 1) sum += __shfl_down_sync(0xffffffffu, sum, o);
            if (lane == 0) {
                *out = sum;
                g_done = 0u;                    // reset counter for next replay
            }
        }
    }
}

extern "C" void kernel_launch(void* const* d_in, const int* in_sizes, int n_in,
                              void* d_out, int out_size) {
    const float* img = (const float*)d_in[0];   // (32,1,1024,1024) fp32
    const int*   bb  = (const int*)d_in[1];     // (32,96,4) int32
    float* out = (float*)d_out;

    fused_kernel<<<GRID, NTHREADS>>>(img, bb, out);
}